// round 2
// baseline (speedup 1.0000x reference)
#include <cuda_runtime.h>
#include <cuda_fp16.h>
#include <cstdint>
#include <cstddef>

// ============================================================================
// Problem dims
//   out[t,m] = sum_j xr[t,j] * Wcat[m,j],  xr = [x@Pi1^T | x@Pi2^T]  (K = 8192)
//   xr[t,j]  = sum_k x[t,k]  * Pcat[j,k]   (Pcat = [Pi1; Pi2], N = 8192, K = 4096)
// ============================================================================
#define TOK    512
#define NF     4096
#define KSTEP  32           // halves of K per pipeline stage
#define NSTG   4
#define ROWPAD 40           // halves per smem row (32 data + 8 pad) = 80 B
#define ROWP32 20           // same in b32 units
#define SMEM_BYTES (NSTG * 2 * 128 * ROWPAD * 2)   // 81920

// ============================================================================
// Device scratch (no cudaMalloc allowed)
// ============================================================================
static __device__ __half g_x16[(size_t)TOK * NF];          //  4 MB  x  (fp16)
static __device__ __half g_P16[(size_t)2 * NF * NF];       // 64 MB  [Pi1; Pi2]
static __device__ __half g_W16[(size_t)NF * 2 * NF];       // 64 MB  [W1 | W2] per row
static __device__ __half g_xr [(size_t)TOK * 2 * NF];      //  8 MB  [xr1 | xr2]

// ============================================================================
// Prep kernels
// ============================================================================
__global__ void tq_f2h(const float4* __restrict__ in, __half2* __restrict__ out, int n4) {
    int i = blockIdx.x * blockDim.x + threadIdx.x;
    if (i >= n4) return;
    float4 v = in[i];
    out[2 * i]     = __floats2half2_rn(v.x, v.y);
    out[2 * i + 1] = __floats2half2_rn(v.z, v.w);
}

// 4-bit unpack + codebook gather + group-norm scale -> fp16, column block koff
__global__ void tq_dequant(const int* __restrict__ IP, const float* __restrict__ NRM,
                           const float* __restrict__ CB, __half* __restrict__ O, int koff) {
    int i = blockIdx.x * blockDim.x + threadIdx.x;   // over 4096 * 2048 packed ints
    if (i >= NF * (NF / 2)) return;
    int m  = i >> 11;
    int ci = i & 2047;
    int p  = IP[i];
    float s  = __ldg(&NRM[(m << 5) + (ci >> 6)]) * 0.08838834764831843f; // 1/sqrt(128)
    float w0 = __ldg(&CB[p & 15]) * s;
    float w1 = __ldg(&CB[(p >> 4) & 15]) * s;
    reinterpret_cast<__half2*>(O + (size_t)m * (2 * NF) + koff)[ci] = __floats2half2_rn(w0, w1);
}

// ============================================================================
// HMMA fp16 GEMM:  C[tBase+i, jBase+j] = sum_k X[tBase+i, k] * W[jBase+j, k]
//   256 threads, tile 128(t) x 128(j), K-step 32, 4-stage cp.async pipeline.
//   Warp grid 2(m) x 4(n); per warp 64x32 via mma.m16n8k16 (4x4 tiles).
//   Cf != nullptr -> fp32 store; else fp16 store to Ch.
// ============================================================================
__global__ void __launch_bounds__(256, 1)
tq_hgemm(const __half* __restrict__ X, int ldx,
         const __half* __restrict__ W, int ldw,
         int ksteps,
         float* __restrict__ Cf, __half* __restrict__ Ch, int ldc)
{
    extern __shared__ __align__(16) char dsm[];
    __half* sm = reinterpret_cast<__half*>(dsm);

    const int tid  = threadIdx.x;
    const int wid  = tid >> 5;
    const int lid  = tid & 31;
    const int wm   = wid >> 2;           // 0..1  (t-halves of 64)
    const int wn   = wid & 3;            // 0..3  (j-quarters of 32)
    const int g    = lid >> 2;           // group id 0..7
    const int tg   = lid & 3;            // thread-in-group 0..3
    const int jBase = blockIdx.x * 128;
    const int tBase = blockIdx.y * 128;

    const __half* xb = X + (size_t)tBase * ldx;
    const __half* wb = W + (size_t)jBase * ldw;

    const int stageHalves = 2 * 128 * ROWPAD;   // X tile + W tile

    // ---- stage loader: 1024 x 16B chunks, 4 per thread
    auto load_stage = [&](int slot, int step) {
        const int k0 = step * KSTEP;
        #pragma unroll
        for (int s = 0; s < 4; ++s) {
            int c  = tid + s * 256;
            int op = c >> 9;              // 0 = X, 1 = W
            int r  = (c >> 2) & 127;      // tile row
            int ch = c & 3;               // 16B chunk in 64B row
            const __half* src = (op ? wb + (size_t)r * ldw
                                    : xb + (size_t)r * ldx) + k0 + ch * 8;
            __half* dst = sm + slot * stageHalves + op * 128 * ROWPAD
                        + r * ROWPAD + ch * 8;
            uint32_t da;
            asm("{ .reg .u64 t; cvta.to.shared.u64 t, %1; cvt.u32.u64 %0, t; }"
                : "=r"(da) : "l"(dst));
            asm volatile("cp.async.cg.shared.global [%0], [%1], 16;"
                         :: "r"(da), "l"(src));
        }
    };

    float acc[4][4][4];
    #pragma unroll
    for (int a = 0; a < 4; ++a)
        #pragma unroll
        for (int b = 0; b < 4; ++b)
            #pragma unroll
            for (int c = 0; c < 4; ++c) acc[a][b][c] = 0.f;

    // ---- prefetch
    #pragma unroll
    for (int p = 0; p < NSTG - 1; ++p) {
        load_stage(p, p);
        asm volatile("cp.async.commit_group;" ::: "memory");
    }

    for (int it = 0; it < ksteps; ++it) {
        __syncthreads();   // all warps done with slot (it-1)&3
        const int pf = it + NSTG - 1;
        if (pf < ksteps) load_stage(pf & 3, pf);
        asm volatile("cp.async.commit_group;" ::: "memory");
        asm volatile("cp.async.wait_group %0;" :: "n"(NSTG - 1) : "memory");
        __syncthreads();   // slot it&3 visible to all

        const uint32_t* xs32 = reinterpret_cast<const uint32_t*>(sm + (it & 3) * stageHalves);
        const uint32_t* ws32 = xs32 + 128 * ROWP32;

        #pragma unroll
        for (int kk = 0; kk < 2; ++kk) {          // two k16 halves of the K-step
            const int kb = kk * 8;                // b32 offset within row
            uint32_t af[4][4];
            #pragma unroll
            for (int mi = 0; mi < 4; ++mi) {
                int row = wm * 64 + mi * 16 + g;
                af[mi][0] = xs32[row * ROWP32 + kb + tg];
                af[mi][1] = xs32[(row + 8) * ROWP32 + kb + tg];
                af[mi][2] = xs32[row * ROWP32 + kb + 4 + tg];
                af[mi][3] = xs32[(row + 8) * ROWP32 + kb + 4 + tg];
            }
            uint32_t bf[4][2];
            #pragma unroll
            for (int ni = 0; ni < 4; ++ni) {
                int rn = wn * 32 + ni * 8 + g;
                bf[ni][0] = ws32[rn * ROWP32 + kb + tg];
                bf[ni][1] = ws32[rn * ROWP32 + kb + 4 + tg];
            }
            #pragma unroll
            for (int mi = 0; mi < 4; ++mi)
                #pragma unroll
                for (int ni = 0; ni < 4; ++ni) {
                    asm volatile(
                        "mma.sync.aligned.m16n8k16.row.col.f32.f16.f16.f32 "
                        "{%0,%1,%2,%3}, {%4,%5,%6,%7}, {%8,%9}, {%0,%1,%2,%3};"
                        : "+f"(acc[mi][ni][0]), "+f"(acc[mi][ni][1]),
                          "+f"(acc[mi][ni][2]), "+f"(acc[mi][ni][3])
                        : "r"(af[mi][0]), "r"(af[mi][1]), "r"(af[mi][2]), "r"(af[mi][3]),
                          "r"(bf[ni][0]), "r"(bf[ni][1]));
                }
        }
    }

    // ---- epilogue
    #pragma unroll
    for (int mi = 0; mi < 4; ++mi) {
        #pragma unroll
        for (int ni = 0; ni < 4; ++ni) {
            int row = tBase + wm * 64 + mi * 16 + g;
            int col = jBase + wn * 32 + ni * 8 + tg * 2;
            if (Cf) {
                float2 v0 = make_float2(acc[mi][ni][0], acc[mi][ni][1]);
                float2 v1 = make_float2(acc[mi][ni][2], acc[mi][ni][3]);
                *reinterpret_cast<float2*>(Cf + (size_t)row * ldc + col)       = v0;
                *reinterpret_cast<float2*>(Cf + (size_t)(row + 8) * ldc + col) = v1;
            } else {
                __half2 h0 = __floats2half2_rn(acc[mi][ni][0], acc[mi][ni][1]);
                __half2 h1 = __floats2half2_rn(acc[mi][ni][2], acc[mi][ni][3]);
                *reinterpret_cast<__half2*>(Ch + (size_t)row * ldc + col)       = h0;
                *reinterpret_cast<__half2*>(Ch + (size_t)(row + 8) * ldc + col) = h1;
            }
        }
    }
}

// ============================================================================
// Launch
// ============================================================================
extern "C" void kernel_launch(void* const* d_in, const int* in_sizes, int n_in,
                              void* d_out, int out_size) {
    (void)in_sizes; (void)n_in; (void)out_size;
    const float* x    = (const float*)d_in[0];
    const float* Pi   = (const float*)d_in[1];
    const int*   idx1 = (const int*)  d_in[2];
    const float* nrm1 = (const float*)d_in[3];
    const float* cb1  = (const float*)d_in[4];
    const int*   idx2 = (const int*)  d_in[5];
    const float* nrm2 = (const float*)d_in[6];
    const float* cb2  = (const float*)d_in[7];
    const float* Pi2  = (const float*)d_in[8];
    float* out = (float*)d_out;

    __half *px16, *pP16, *pW16, *pxr;
    cudaGetSymbolAddress((void**)&px16, g_x16);
    cudaGetSymbolAddress((void**)&pP16, g_P16);
    cudaGetSymbolAddress((void**)&pW16, g_W16);
    cudaGetSymbolAddress((void**)&pxr,  g_xr);

    cudaFuncSetAttribute(tq_hgemm, cudaFuncAttributeMaxDynamicSharedMemorySize,
                         SMEM_BYTES);

    // ---- prep: fp32->fp16 conversions + dequant
    const int n4x = TOK * NF / 4;
    const int n4p = NF * NF / 4;
    tq_f2h<<<(n4x + 255) / 256, 256>>>((const float4*)x,   (__half2*)px16, n4x);
    tq_f2h<<<(n4p + 255) / 256, 256>>>((const float4*)Pi,  (__half2*)pP16, n4p);
    tq_f2h<<<(n4p + 255) / 256, 256>>>((const float4*)Pi2, (__half2*)(pP16 + (size_t)NF * NF), n4p);
    const int ndq = NF * (NF / 2);
    tq_dequant<<<(ndq + 255) / 256, 256>>>(idx1, nrm1, cb1, pW16, 0);
    tq_dequant<<<(ndq + 255) / 256, 256>>>(idx2, nrm2, cb2, pW16, NF);

    // ---- GEMM1: xr[512, 8192] = x16 @ Pcat^T   (K = 4096)
    {
        dim3 grid(2 * NF / 128, TOK / 128);   // (64, 4)
        tq_hgemm<<<grid, 256, SMEM_BYTES>>>(px16, NF, pP16, NF,
                                            NF / KSTEP, nullptr, pxr, 2 * NF);
    }
    // ---- GEMM2: out[512, 4096] = xr @ Wcat^T   (K = 8192)
    {
        dim3 grid(NF / 128, TOK / 128);       // (32, 4)
        tq_hgemm<<<grid, 256, SMEM_BYTES>>>(pxr, 2 * NF, pW16, 2 * NF,
                                            2 * NF / KSTEP, out, nullptr, NF);
    }
}

// round 3
// speedup vs baseline: 1.6488x; 1.6488x over previous
#include <cuda_runtime.h>
#include <cuda_fp16.h>
#include <cstdint>
#include <cstddef>

// ============================================================================
//   out[t,m] = sum_j xr[t,j] * Wcat[m,j],  xr = [x@Pi1^T | x@Pi2^T]  (K = 8192)
//   xr[t,j]  = sum_k x[t,k]  * Pcat[j,k]   (Pcat = [Pi1; Pi2], N = 8192, K = 4096)
// ============================================================================
#define TOK    512
#define NF     4096
#define KSTEP  64                         // halves of K per pipeline stage (128 B rows)
#define NSTG   4
#define STAGE_BYTES (256 * 128)           // 128 X rows + 128 W rows, 128 B each
#define SMEM_BYTES  (NSTG * STAGE_BYTES)  // 131072

// ============================================================================
// Device scratch (no cudaMalloc allowed)
// ============================================================================
static __device__ __half g_x16[(size_t)TOK * NF];          //  4 MB
static __device__ __half g_P16[(size_t)2 * NF * NF];       // 64 MB  [Pi1; Pi2]
static __device__ __half g_W16[(size_t)NF * 2 * NF];       // 64 MB  [W1 | W2] per row
static __device__ __half g_xr [(size_t)TOK * 2 * NF];      //  8 MB  [xr1 | xr2]

static __device__ __forceinline__ uint32_t smem_u32(const void* p) {
    uint32_t a;
    asm("{ .reg .u64 t; cvta.to.shared.u64 t, %1; cvt.u32.u64 %0, t; }"
        : "=r"(a) : "l"(p));
    return a;
}

#define TQ_LDSM4(r0, r1, r2, r3, addr) \
    asm volatile("ldmatrix.sync.aligned.m8n8.x4.shared.b16 {%0,%1,%2,%3}, [%4];" \
                 : "=r"(r0), "=r"(r1), "=r"(r2), "=r"(r3) : "r"(addr))

// ============================================================================
// Prep kernels
// ============================================================================
__global__ void tq_f2h(const float4* __restrict__ in, __half2* __restrict__ out, int n4) {
    int i = blockIdx.x * (blockDim.x * 4) + threadIdx.x;
    #pragma unroll
    for (int j = 0; j < 4; ++j) {
        int k = i + j * blockDim.x;
        if (k < n4) {
            float4 v = in[k];
            out[2 * k]     = __floats2half2_rn(v.x, v.y);
            out[2 * k + 1] = __floats2half2_rn(v.z, v.w);
        }
    }
}

// 4-bit unpack + codebook + group norm -> fp16 at column offset koff.
// Each int32 holds one byte (2 nibbles -> 2 columns). int4 -> 8 halves (16 B).
__global__ void tq_dequant(const int4* __restrict__ IP4, const float* __restrict__ NRM,
                           const float* __restrict__ CB, __half* __restrict__ O, int koff) {
    __shared__ float cb[16];
    if (threadIdx.x < 16) cb[threadIdx.x] = CB[threadIdx.x];
    __syncthreads();
    int i = blockIdx.x * blockDim.x + threadIdx.x;      // over NF*(NF/2)/4 int4
    if (i >= NF * (NF / 2) / 4) return;
    int m  = i >> 9;          // 512 int4 per row
    int c4 = i & 511;         // int4 index within row
    int4 p = IP4[i];
    float s = __ldg(&NRM[(m << 5) + (c4 >> 4)]) * 0.08838834764831843f;  // 1/sqrt(128)
    __half2 h[4];
    h[0] = __floats2half2_rn(cb[p.x & 15] * s, cb[(p.x >> 4) & 15] * s);
    h[1] = __floats2half2_rn(cb[p.y & 15] * s, cb[(p.y >> 4) & 15] * s);
    h[2] = __floats2half2_rn(cb[p.z & 15] * s, cb[(p.z >> 4) & 15] * s);
    h[3] = __floats2half2_rn(cb[p.w & 15] * s, cb[(p.w >> 4) & 15] * s);
    *reinterpret_cast<uint4*>(O + (size_t)m * (2 * NF) + koff + c4 * 8) =
        *reinterpret_cast<uint4*>(h);
}

// ============================================================================
// HMMA fp16 GEMM:  C[tBase+i, jBase+j] = sum_k X[tBase+i, k] * W[jBase+j, k]
//   256 threads; tile 128(t) x 128(j); K-step 64; 4-stage cp.async pipeline;
//   XOR-swizzled 128B smem rows; ldmatrix.x4 fragment loads; warp tile 64x32.
// ============================================================================
__global__ void __launch_bounds__(256, 1)
tq_hgemm(const __half* __restrict__ X, int ldx,
         const __half* __restrict__ W, int ldw,
         int ksteps,
         float* __restrict__ Cf, __half* __restrict__ Ch, int ldc)
{
    extern __shared__ __align__(1024) char dsm[];
    const uint32_t smBase = smem_u32(dsm);

    const int tid = threadIdx.x;
    const int wid = tid >> 5;
    const int lid = tid & 31;
    const int wm  = wid >> 2;            // 0..1
    const int wn  = wid & 3;             // 0..3
    const int jBase = blockIdx.x * 128;
    const int tBase = blockIdx.y * 128;

    const __half* xb = X + (size_t)tBase * ldx;
    const __half* wb = W + (size_t)jBase * ldw;

    // ---- stage loader: 2048 x 16B chunks, 8 per thread, swizzled rows
    auto load_stage = [&](int slot, int step) {
        const int k0 = step * KSTEP;
        #pragma unroll
        for (int s = 0; s < 8; ++s) {
            int q  = tid + s * 256;
            int r  = q >> 3;             // 0..255 (128 X rows then 128 W rows)
            int c  = q & 7;              // 16B chunk in 128B row
            int rt = r & 127;
            const __half* src = ((r >> 7) ? wb + (size_t)rt * ldw
                                          : xb + (size_t)rt * ldx) + k0 + c * 8;
            uint32_t dst = smBase + slot * STAGE_BYTES + r * 128 + ((c ^ (r & 7)) * 16);
            asm volatile("cp.async.cg.shared.global [%0], [%1], 16;"
                         :: "r"(dst), "l"(src));
        }
    };

    // ---- per-lane ldmatrix row/parity mapping (see fragment layout notes)
    const int swz  = lid & 7;
    const int rowA = wm * 64 + (lid & 7) + ((lid >> 3) & 1) * 8;          // X region
    const int pA   = lid >> 4;
    const int rowB = 128 + wn * 32 + (lid & 7) + ((lid >> 4) & 1) * 8;    // W region
    const int pB   = (lid >> 3) & 1;

    float acc[4][4][4];
    #pragma unroll
    for (int a = 0; a < 4; ++a)
        #pragma unroll
        for (int b = 0; b < 4; ++b)
            #pragma unroll
            for (int c = 0; c < 4; ++c) acc[a][b][c] = 0.f;

    // ---- prologue: fill NSTG-1 stages
    #pragma unroll
    for (int p = 0; p < NSTG - 1; ++p) {
        load_stage(p, p);
        asm volatile("cp.async.commit_group;" ::: "memory");
    }

    for (int it = 0; it < ksteps; ++it) {
        asm volatile("cp.async.wait_group %0;" :: "n"(NSTG - 2) : "memory");
        __syncthreads();

        const int pf = it + NSTG - 1;
        if (pf < ksteps) load_stage(pf & (NSTG - 1), pf);
        asm volatile("cp.async.commit_group;" ::: "memory");

        const uint32_t sb = smBase + (it & (NSTG - 1)) * STAGE_BYTES;

        #pragma unroll
        for (int kb = 0; kb < 4; ++kb) {       // 4 x k16 per K-step
            uint32_t a[4][4];
            #pragma unroll
            for (int mi = 0; mi < 4; ++mi) {
                uint32_t ad = sb + (uint32_t)(rowA + mi * 16) * 128
                            + (uint32_t)(((kb * 2 + pA) ^ swz) * 16);
                TQ_LDSM4(a[mi][0], a[mi][1], a[mi][2], a[mi][3], ad);
            }
            uint32_t b[4][2];
            #pragma unroll
            for (int gi = 0; gi < 2; ++gi) {
                uint32_t bd = sb + (uint32_t)(rowB + gi * 16) * 128
                            + (uint32_t)(((kb * 2 + pB) ^ swz) * 16);
                TQ_LDSM4(b[2 * gi][0], b[2 * gi][1], b[2 * gi + 1][0], b[2 * gi + 1][1], bd);
            }
            #pragma unroll
            for (int mi = 0; mi < 4; ++mi)
                #pragma unroll
                for (int ni = 0; ni < 4; ++ni) {
                    asm volatile(
                        "mma.sync.aligned.m16n8k16.row.col.f32.f16.f16.f32 "
                        "{%0,%1,%2,%3}, {%4,%5,%6,%7}, {%8,%9}, {%0,%1,%2,%3};"
                        : "+f"(acc[mi][ni][0]), "+f"(acc[mi][ni][1]),
                          "+f"(acc[mi][ni][2]), "+f"(acc[mi][ni][3])
                        : "r"(a[mi][0]), "r"(a[mi][1]), "r"(a[mi][2]), "r"(a[mi][3]),
                          "r"(b[ni][0]), "r"(b[ni][1]));
                }
        }
    }

    // ---- epilogue
    const int g  = lid >> 2;
    const int tg = lid & 3;
    #pragma unroll
    for (int mi = 0; mi < 4; ++mi) {
        #pragma unroll
        for (int ni = 0; ni < 4; ++ni) {
            int row = tBase + wm * 64 + mi * 16 + g;
            int col = jBase + wn * 32 + ni * 8 + tg * 2;
            if (Cf) {
                float2 v0 = make_float2(acc[mi][ni][0], acc[mi][ni][1]);
                float2 v1 = make_float2(acc[mi][ni][2], acc[mi][ni][3]);
                *reinterpret_cast<float2*>(Cf + (size_t)row * ldc + col)       = v0;
                *reinterpret_cast<float2*>(Cf + (size_t)(row + 8) * ldc + col) = v1;
            } else {
                __half2 h0 = __floats2half2_rn(acc[mi][ni][0], acc[mi][ni][1]);
                __half2 h1 = __floats2half2_rn(acc[mi][ni][2], acc[mi][ni][3]);
                *reinterpret_cast<__half2*>(Ch + (size_t)row * ldc + col)       = h0;
                *reinterpret_cast<__half2*>(Ch + (size_t)(row + 8) * ldc + col) = h1;
            }
        }
    }
}

// ============================================================================
// Launch
// ============================================================================
extern "C" void kernel_launch(void* const* d_in, const int* in_sizes, int n_in,
                              void* d_out, int out_size) {
    (void)in_sizes; (void)n_in; (void)out_size;
    const float* x    = (const float*)d_in[0];
    const float* Pi   = (const float*)d_in[1];
    const int*   idx1 = (const int*)  d_in[2];
    const float* nrm1 = (const float*)d_in[3];
    const float* cb1  = (const float*)d_in[4];
    const int*   idx2 = (const int*)  d_in[5];
    const float* nrm2 = (const float*)d_in[6];
    const float* cb2  = (const float*)d_in[7];
    const float* Pi2  = (const float*)d_in[8];
    float* out = (float*)d_out;

    __half *px16, *pP16, *pW16, *pxr;
    cudaGetSymbolAddress((void**)&px16, g_x16);
    cudaGetSymbolAddress((void**)&pP16, g_P16);
    cudaGetSymbolAddress((void**)&pW16, g_W16);
    cudaGetSymbolAddress((void**)&pxr,  g_xr);

    cudaFuncSetAttribute(tq_hgemm, cudaFuncAttributeMaxDynamicSharedMemorySize,
                         SMEM_BYTES);

    // ---- prep
    const int n4x = TOK * NF / 4;
    const int n4p = NF * NF / 4;
    tq_f2h<<<(n4x + 1023) / 1024, 256>>>((const float4*)x,   (__half2*)px16, n4x);
    tq_f2h<<<(n4p + 1023) / 1024, 256>>>((const float4*)Pi,  (__half2*)pP16, n4p);
    tq_f2h<<<(n4p + 1023) / 1024, 256>>>((const float4*)Pi2,
                                         (__half2*)(pP16 + (size_t)NF * NF), n4p);
    const int ndq4 = NF * (NF / 2) / 4;
    tq_dequant<<<(ndq4 + 255) / 256, 256>>>((const int4*)idx1, nrm1, cb1, pW16, 0);
    tq_dequant<<<(ndq4 + 255) / 256, 256>>>((const int4*)idx2, nrm2, cb2, pW16, NF);

    // ---- GEMM1: xr[512, 8192] = x16 @ Pcat^T   (K = 4096)
    {
        dim3 grid(2 * NF / 128, TOK / 128);   // (64, 4)
        tq_hgemm<<<grid, 256, SMEM_BYTES>>>(px16, NF, pP16, NF,
                                            NF / KSTEP, nullptr, pxr, 2 * NF);
    }
    // ---- GEMM2: out[512, 4096] = xr @ Wcat^T   (K = 8192)
    {
        dim3 grid(NF / 128, TOK / 128);       // (32, 4)
        tq_hgemm<<<grid, 256, SMEM_BYTES>>>(pxr, 2 * NF, pW16, 2 * NF,
                                            2 * NF / KSTEP, out, nullptr, NF);
    }
}

// round 4
// speedup vs baseline: 1.7993x; 1.0913x over previous
#include <cuda_runtime.h>
#include <cuda_fp16.h>
#include <cstdint>
#include <cstddef>

// ============================================================================
//   out[t,m] = sum_j xr[t,j] * Wcat[m,j],  xr = [x@Pi1^T | x@Pi2^T]  (K = 8192)
//   xr[t,j]  = sum_k x[t,k]  * Pcat[j,k]   (Pcat = [Pi1; Pi2], N = 8192, K = 4096)
// ============================================================================
#define TOK    512
#define NF     4096
#define KSTEP  64                          // halves of K per stage (128 B rows)
#define NSTG   4
#define TT     128                         // token rows per CTA
#define TJ     256                         // j rows per CTA
#define STAGE_ROWS (TT + TJ)               // 384
#define STAGE_BYTES (STAGE_ROWS * 128)     // 49152
#define SMEM_BYTES  (NSTG * STAGE_BYTES)   // 196608

// ============================================================================
// Device scratch (no cudaMalloc allowed)
// ============================================================================
static __device__ __half g_x16[(size_t)TOK * NF];          //  4 MB
static __device__ __half g_P16[(size_t)2 * NF * NF];       // 64 MB  [Pi1; Pi2]
static __device__ __half g_W16[(size_t)NF * 2 * NF];       // 64 MB  [W1 | W2] per row
static __device__ __half g_xr [(size_t)TOK * 2 * NF];      //  8 MB  [xr1 | xr2]

static __device__ __forceinline__ uint32_t smem_u32(const void* p) {
    uint32_t a;
    asm("{ .reg .u64 t; cvta.to.shared.u64 t, %1; cvt.u32.u64 %0, t; }"
        : "=r"(a) : "l"(p));
    return a;
}

#define TQ_LDSM4(r0, r1, r2, r3, addr) \
    asm volatile("ldmatrix.sync.aligned.m8n8.x4.shared.b16 {%0,%1,%2,%3}, [%4];" \
                 : "=r"(r0), "=r"(r1), "=r"(r2), "=r"(r3) : "r"(addr))

// ============================================================================
// Prep kernels
// ============================================================================
__global__ void tq_f2h(const float4* __restrict__ in, __half2* __restrict__ out, int n4) {
    int i = blockIdx.x * (blockDim.x * 4) + threadIdx.x;
    #pragma unroll
    for (int j = 0; j < 4; ++j) {
        int k = i + j * blockDim.x;
        if (k < n4) {
            float4 v = in[k];
            out[2 * k]     = __floats2half2_rn(v.x, v.y);
            out[2 * k + 1] = __floats2half2_rn(v.z, v.w);
        }
    }
}

__global__ void tq_zero(float4* __restrict__ p, int n4) {
    int i = blockIdx.x * blockDim.x + threadIdx.x;
    if (i < n4) p[i] = make_float4(0.f, 0.f, 0.f, 0.f);
}

// 4-bit unpack + codebook + group norm -> fp16 at column offset koff.
// Two int4 per thread for MLP.
__global__ void tq_dequant(const int4* __restrict__ IP4, const float* __restrict__ NRM,
                           const float* __restrict__ CB, __half* __restrict__ O, int koff) {
    __shared__ float cb[16];
    if (threadIdx.x < 16) cb[threadIdx.x] = CB[threadIdx.x];
    __syncthreads();
    int base = blockIdx.x * 512 + threadIdx.x;
    #pragma unroll
    for (int u = 0; u < 2; ++u) {
        int i = base + u * 256;
        if (i >= NF * (NF / 2) / 4) return;
        int m  = i >> 9;
        int c4 = i & 511;
        int4 p = IP4[i];
        float s = __ldg(&NRM[(m << 5) + (c4 >> 4)]) * 0.08838834764831843f;
        __half2 h[4];
        h[0] = __floats2half2_rn(cb[p.x & 15] * s, cb[(p.x >> 4) & 15] * s);
        h[1] = __floats2half2_rn(cb[p.y & 15] * s, cb[(p.y >> 4) & 15] * s);
        h[2] = __floats2half2_rn(cb[p.z & 15] * s, cb[(p.z >> 4) & 15] * s);
        h[3] = __floats2half2_rn(cb[p.w & 15] * s, cb[(p.w >> 4) & 15] * s);
        *reinterpret_cast<uint4*>(O + (size_t)m * (2 * NF) + koff + c4 * 8) =
            *reinterpret_cast<uint4*>(h);
    }
}

// ============================================================================
// HMMA fp16 GEMM: tile TT(t) x TJ(j); 8 warps in grid 2(t) x 4(j); warp 64x64.
//   C[t, j] = sum_k X[t, k] * W[j, k];  K window [kOff, kOff + ksteps*KSTEP).
//   Ch != nullptr: fp16 store.   Cf != nullptr: fp32 atomicAdd (split-K).
// ============================================================================
__global__ void __launch_bounds__(256, 1)
tq_hgemm(const __half* __restrict__ X, int ldx,
         const __half* __restrict__ W, int ldw,
         int ksteps,
         float* __restrict__ Cf, __half* __restrict__ Ch, int ldc)
{
    extern __shared__ __align__(1024) char dsm[];
    const uint32_t smBase = smem_u32(dsm);

    const int tid = threadIdx.x;
    const int wid = tid >> 5;
    const int lid = tid & 31;
    const int wm  = wid >> 2;            // 0..1
    const int wn  = wid & 3;             // 0..3
    const int jBase = blockIdx.x * TJ;
    const int tBase = blockIdx.y * TT;
    const int kOff  = blockIdx.z * (ksteps * KSTEP);

    const __half* xb = X + (size_t)tBase * ldx + kOff;
    const __half* wb = W + (size_t)jBase * ldw + kOff;

    // ---- stage loader: 3072 x 16B chunks, 12 per thread, swizzled rows
    auto load_stage = [&](int slot, int step) {
        const int k0 = step * KSTEP;
        #pragma unroll
        for (int s = 0; s < 12; ++s) {
            int q = tid + s * 256;
            int r = q >> 3;              // 0..383 (128 X rows then 256 W rows)
            int c = q & 7;
            const __half* src = (r < TT ? xb + (size_t)r * ldx
                                        : wb + (size_t)(r - TT) * ldw) + k0 + c * 8;
            uint32_t dst = smBase + slot * STAGE_BYTES + r * 128 + ((c ^ (r & 7)) * 16);
            asm volatile("cp.async.cg.shared.global [%0], [%1], 16;"
                         :: "r"(dst), "l"(src));
        }
    };

    // ---- per-lane ldmatrix mappings (verified in round 2)
    const int swz  = lid & 7;
    const int rowA = wm * 64 + (lid & 7) + ((lid >> 3) & 1) * 8;        // X region
    const int pA   = lid >> 4;
    const int rowB = TT + wn * 64 + (lid & 7) + ((lid >> 4) & 1) * 8;   // W region
    const int pB   = (lid >> 3) & 1;

    float acc[4][8][4];
    #pragma unroll
    for (int a = 0; a < 4; ++a)
        #pragma unroll
        for (int b = 0; b < 8; ++b)
            #pragma unroll
            for (int c = 0; c < 4; ++c) acc[a][b][c] = 0.f;

    #pragma unroll
    for (int p = 0; p < NSTG - 1; ++p) {
        load_stage(p, p);
        asm volatile("cp.async.commit_group;" ::: "memory");
    }

    for (int it = 0; it < ksteps; ++it) {
        asm volatile("cp.async.wait_group %0;" :: "n"(NSTG - 2) : "memory");
        __syncthreads();

        const int pf = it + NSTG - 1;
        if (pf < ksteps) load_stage(pf & (NSTG - 1), pf);
        asm volatile("cp.async.commit_group;" ::: "memory");

        const uint32_t sb = smBase + (it & (NSTG - 1)) * STAGE_BYTES;

        #pragma unroll
        for (int kb = 0; kb < 4; ++kb) {       // 4 x k16 per K-step
            uint32_t a[4][4];
            #pragma unroll
            for (int mi = 0; mi < 4; ++mi) {
                uint32_t ad = sb + (uint32_t)(rowA + mi * 16) * 128
                            + (uint32_t)(((kb * 2 + pA) ^ swz) * 16);
                TQ_LDSM4(a[mi][0], a[mi][1], a[mi][2], a[mi][3], ad);
            }
            uint32_t b[8][2];
            #pragma unroll
            for (int gi = 0; gi < 4; ++gi) {
                uint32_t bd = sb + (uint32_t)(rowB + gi * 16) * 128
                            + (uint32_t)(((kb * 2 + pB) ^ swz) * 16);
                TQ_LDSM4(b[2 * gi][0], b[2 * gi][1], b[2 * gi + 1][0], b[2 * gi + 1][1], bd);
            }
            #pragma unroll
            for (int mi = 0; mi < 4; ++mi)
                #pragma unroll
                for (int ni = 0; ni < 8; ++ni) {
                    asm volatile(
                        "mma.sync.aligned.m16n8k16.row.col.f32.f16.f16.f32 "
                        "{%0,%1,%2,%3}, {%4,%5,%6,%7}, {%8,%9}, {%0,%1,%2,%3};"
                        : "+f"(acc[mi][ni][0]), "+f"(acc[mi][ni][1]),
                          "+f"(acc[mi][ni][2]), "+f"(acc[mi][ni][3])
                        : "r"(a[mi][0]), "r"(a[mi][1]), "r"(a[mi][2]), "r"(a[mi][3]),
                          "r"(b[ni][0]), "r"(b[ni][1]));
                }
        }
    }

    // ---- epilogue
    const int g  = lid >> 2;
    const int tg = lid & 3;
    #pragma unroll
    for (int mi = 0; mi < 4; ++mi) {
        #pragma unroll
        for (int ni = 0; ni < 8; ++ni) {
            int row = tBase + wm * 64 + mi * 16 + g;
            int col = jBase + wn * 64 + ni * 8 + tg * 2;
            if (Ch) {
                __half2 h0 = __floats2half2_rn(acc[mi][ni][0], acc[mi][ni][1]);
                __half2 h1 = __floats2half2_rn(acc[mi][ni][2], acc[mi][ni][3]);
                *reinterpret_cast<__half2*>(Ch + (size_t)row * ldc + col)       = h0;
                *reinterpret_cast<__half2*>(Ch + (size_t)(row + 8) * ldc + col) = h1;
            } else {
                atomicAdd(Cf + (size_t)row * ldc + col,           acc[mi][ni][0]);
                atomicAdd(Cf + (size_t)row * ldc + col + 1,       acc[mi][ni][1]);
                atomicAdd(Cf + (size_t)(row + 8) * ldc + col,     acc[mi][ni][2]);
                atomicAdd(Cf + (size_t)(row + 8) * ldc + col + 1, acc[mi][ni][3]);
            }
        }
    }
}

// ============================================================================
// Launch   (order chosen so launch index 4 (ncu capture point) = GEMM1)
// ============================================================================
extern "C" void kernel_launch(void* const* d_in, const int* in_sizes, int n_in,
                              void* d_out, int out_size) {
    (void)in_sizes; (void)n_in; (void)out_size;
    const float* x    = (const float*)d_in[0];
    const float* Pi   = (const float*)d_in[1];
    const int*   idx1 = (const int*)  d_in[2];
    const float* nrm1 = (const float*)d_in[3];
    const float* cb1  = (const float*)d_in[4];
    const int*   idx2 = (const int*)  d_in[5];
    const float* nrm2 = (const float*)d_in[6];
    const float* cb2  = (const float*)d_in[7];
    const float* Pi2  = (const float*)d_in[8];
    float* out = (float*)d_out;

    __half *px16, *pP16, *pW16, *pxr;
    cudaGetSymbolAddress((void**)&px16, g_x16);
    cudaGetSymbolAddress((void**)&pP16, g_P16);
    cudaGetSymbolAddress((void**)&pW16, g_W16);
    cudaGetSymbolAddress((void**)&pxr,  g_xr);

    cudaFuncSetAttribute(tq_hgemm, cudaFuncAttributeMaxDynamicSharedMemorySize,
                         SMEM_BYTES);

    const int n4x  = TOK * NF / 4;
    const int n4p  = NF * NF / 4;
    const int ndq4 = NF * (NF / 2) / 4;

    // idx 0-3: prep needed by GEMM1 (+ dq1)
    tq_f2h<<<(n4x + 1023) / 1024, 256>>>((const float4*)x,   (__half2*)px16, n4x);
    tq_f2h<<<(n4p + 1023) / 1024, 256>>>((const float4*)Pi,  (__half2*)pP16, n4p);
    tq_f2h<<<(n4p + 1023) / 1024, 256>>>((const float4*)Pi2,
                                         (__half2*)(pP16 + (size_t)NF * NF), n4p);
    tq_dequant<<<(ndq4 + 511) / 512, 256>>>((const int4*)idx1, nrm1, cb1, pW16, 0);

    // idx 4: GEMM1  xr[512, 8192] = x16 @ Pcat^T   (K = 4096, 128 CTAs)
    {
        dim3 grid(2 * NF / TJ, TOK / TT, 1);   // (32, 4)
        tq_hgemm<<<grid, 256, SMEM_BYTES>>>(px16, NF, pP16, NF,
                                            NF / KSTEP, nullptr, pxr, 2 * NF);
    }

    // idx 5-6: dq2 + zero out
    tq_dequant<<<(ndq4 + 511) / 512, 256>>>((const int4*)idx2, nrm2, cb2, pW16, NF);
    tq_zero<<<(TOK * NF / 4 + 255) / 256, 256>>>((float4*)out, TOK * NF / 4);

    // idx 7: GEMM2  out[512, 4096] += xr @ Wcat^T  (K = 8192, split-K 2, 128 CTAs)
    {
        dim3 grid(NF / TJ, TOK / TT, 2);       // (16, 4, 2)
        tq_hgemm<<<grid, 256, SMEM_BYTES>>>(pxr, 2 * NF, pW16, 2 * NF,
                                            (2 * NF / KSTEP) / 2, out, nullptr, NF);
    }
}